// round 16
// baseline (speedup 1.0000x reference)
#include <cuda_runtime.h>
#include <float.h>
#include <math.h>

// CropRoi: f (4,64,32,32,32) f32; proposals (96,8) f32; out (96,64,7,7,7) f32.
// Box: c0 = max(floor((c-s/2)/4),0), c1 = min(ceil((c+s/2)/4),32); L in [2,13].
// Adaptive windows per axis: size 1..3, always in-range -> plain max; clamped
// duplicate taps are harmless under max.
//
// Row-structured loads (1 line = 1 wavefront) + full parallelism:
//   warp = (proposal, channel-octet, h-bin j). Per d (warp-uniform) x 8 ch:
//   1..3 row-tap LDGs with lanes = 7 k-bins x 4 clamped w-taps (all lanes in
//   the box row's <=13-float span -> 1-2 lines per LDG), 2 shfl.xor resolve
//   all 7 w-bins, predicated STS to pyr[c][j][d][k]. One barrier, then warp j
//   emits its 49 (i,k) outputs x 8 ch via 3 clamped d-tap LDS + STG.
// Single kernel, inline box math, grid (96,8) x 224 threads.

#define RBINS 7
#define FDIM 32
#define CH 8
#define PK 8                    // k-stride (7 + pad)
#define PJ (14 * PK)            // d-dim 14 slots
#define PC (7 * PJ)             // per-channel pyramid stride

__global__ __launch_bounds__(224)
void crop_pool_kernel(const float* __restrict__ f,
                      const float* __restrict__ props,
                      float* __restrict__ out)
{
    const int n    = blockIdx.x;          // proposal
    const int cg   = blockIdx.y * CH;     // first channel
    const int tid  = threadIdx.x;
    const int lane = tid & 31;
    const int j    = tid >> 5;            // warp = h-bin (0..6)

    __shared__ float pyr[CH * PC];        // 8*7*14*8 floats = 25088 B

    // ---- box bounds (inline, ~60 ALU once per thread) ----
    const float4 pa = __ldg((const float4*)(props + n * 8));
    const float4 pb = __ldg((const float4*)(props + n * 8) + 1);
    const int b = (int)pa.x;

    int c0d, Ld, c0h, Lh, c0w, Lw;
    {
        int lo = (int)floorf((pa.z - pb.y * 0.5f) * 0.25f);
        int hi = (int)ceilf ((pa.z + pb.y * 0.5f) * 0.25f);
        lo = max(lo, 0); hi = min(hi, FDIM); c0d = lo; Ld = max(hi - lo, 1);
    }
    {
        int lo = (int)floorf((pa.w - pb.z * 0.5f) * 0.25f);
        int hi = (int)ceilf ((pa.w + pb.z * 0.5f) * 0.25f);
        lo = max(lo, 0); hi = min(hi, FDIM); c0h = lo; Lh = max(hi - lo, 1);
    }
    {
        int lo = (int)floorf((pb.x - pb.w * 0.5f) * 0.25f);
        int hi = (int)ceilf ((pb.x + pb.w * 0.5f) * 0.25f);
        lo = max(lo, 0); hi = min(hi, FDIM); c0w = lo; Lw = max(hi - lo, 1);
    }

    // ---- this warp's h-window (warp-uniform) ----
    const int hs = (j * Lh) / RBINS;
    const int he = ((j + 1) * Lh + RBINS - 1) / RBINS;
    const int nh = he - hs;               // 1..3

    // ---- lane = (k-bin, tap): clamped w taps, all within the row span ----
    const int kc = min(lane >> 2, RBINS - 1);
    const int ws = (kc * Lw) / RBINS;
    const int we = ((kc + 1) * Lw + RBINS - 1) / RBINS;
    const int wtap = c0w + min(ws + (lane & 3), we - 1);
    const bool wr = ((lane & 3) == 0) && (lane < 28);

    const float* src = f + (((size_t)(b * 64 + cg)) << 15)
                         + ((c0d * FDIM + (c0h + hs)) * FDIM) + wtap;

    float* Pj = pyr + j * PJ + kc;        // + c*PC + d*PK

    // ---- Phase A: pyr[c][j][d][k] = max over h-window(j) x w-window(k) ----
    for (int d = 0; d < Ld; ++d) {
        const float* rp = src + (d << 10);
        float* Pd = Pj + d * PK;
#pragma unroll
        for (int c = 0; c < CH; ++c) {
            const float* rc = rp + (c << 15);
            float v = __ldg(rc);                        // 1-2 lines / warp-LDG
            if (nh > 1) v = fmaxf(v, __ldg(rc + FDIM));
            if (nh > 2) v = fmaxf(v, __ldg(rc + 2 * FDIM));
            v = fmaxf(v, __shfl_xor_sync(0xFFFFFFFFu, v, 1));
            v = fmaxf(v, __shfl_xor_sync(0xFFFFFFFFu, v, 2));
            if (wr) Pd[c * PC] = v;
        }
    }

    __syncthreads();

    // ---- Phase B: warp j -> outputs (i, j, k), 49 cells x 8 channels ----
#pragma unroll
    for (int it = 0; it < 2; ++it) {
        const int cell = it * 32 + lane;
        if (cell < 49) {
            const int i  = cell / RBINS;              // const div -> mul/shift
            const int k2 = cell - i * RBINS;

            const int ds = (i * Ld) / RBINS;
            const int de = ((i + 1) * Ld + RBINS - 1) / RBINS;
            const int d0 = ds * PK;
            const int d1 = min(ds + 1, de - 1) * PK;
            const int d2 = (de - 1) * PK;

            const float* Pb = pyr + j * PJ + k2;
            float* ob = out + (size_t)(n * 64 + cg) * 343
                            + i * 49 + j * RBINS + k2;
#pragma unroll
            for (int c = 0; c < CH; ++c) {
                const float* Pc = Pb + c * PC;
                ob[c * 343] = fmaxf(fmaxf(Pc[d0], Pc[d1]), Pc[d2]);
            }
        }
    }
}

extern "C" void kernel_launch(void* const* d_in, const int* in_sizes, int n_in,
                              void* d_out, int out_size)
{
    const float* f     = (const float*)d_in[0];
    const float* props = (const float*)d_in[2];
    float* out = (float*)d_out;

    const int N = in_sizes[2] / 8;   // 96

    crop_pool_kernel<<<dim3(N, 64 / CH), 224>>>(f, props, out);
}